// round 10
// baseline (speedup 1.0000x reference)
#include <cuda_runtime.h>
#include <cuda_bf16.h>
#include <cstdint>

// Problem constants
#define BATCH   2
#define SEQ     4096
#define DMODEL  1024
#define NHEADS  8
#define DH      128
#define RR      4
#define KMAXK   21
#define MROWS   (BATCH * SEQ)   // 8192

// ---------------------------------------------------------------------------
// Scratch (no cudaMalloc allowed)
// ---------------------------------------------------------------------------
__device__ float g_xproj[(size_t)MROWS * DMODEL];
__device__ __nv_bfloat16 g_xhi[(size_t)MROWS * DMODEL];
__device__ __nv_bfloat16 g_xlo[(size_t)MROWS * DMODEL];
__device__ __nv_bfloat16 g_chi[(size_t)MROWS * DMODEL];
__device__ __nv_bfloat16 g_clo[(size_t)MROWS * DMODEL];
__device__ __nv_bfloat16 g_wihi[(size_t)DMODEL * DMODEL];
__device__ __nv_bfloat16 g_wilo[(size_t)DMODEL * DMODEL];
__device__ __nv_bfloat16 g_wohi[(size_t)DMODEL * DMODEL];
__device__ __nv_bfloat16 g_wolo[(size_t)DMODEL * DMODEL];

// ---------------------------------------------------------------------------
// PTX helpers (sm_80-level only: cp.async, ldmatrix, mma.sync)
// ---------------------------------------------------------------------------
__device__ __forceinline__ uint32_t smem_u32(const void* p) {
    uint32_t a;
    asm("{ .reg .u64 t; cvta.to.shared.u64 t, %1; cvt.u32.u64 %0, t; }"
        : "=r"(a) : "l"(p));
    return a;
}

__device__ __forceinline__ void cp_async16(uint32_t dst, const void* src) {
    asm volatile("cp.async.cg.shared.global [%0], [%1], 16;"
                 :: "r"(dst), "l"(src));
}
#define CP_COMMIT() asm volatile("cp.async.commit_group;" ::: "memory")

__device__ __forceinline__ void ldm_x4(uint32_t& r0, uint32_t& r1,
                                       uint32_t& r2, uint32_t& r3, uint32_t addr) {
    asm volatile("ldmatrix.sync.aligned.m8n8.x4.shared.b16 {%0,%1,%2,%3}, [%4];"
                 : "=r"(r0), "=r"(r1), "=r"(r2), "=r"(r3) : "r"(addr));
}

__device__ __forceinline__ void mma16816(float& c0, float& c1, float& c2, float& c3,
                                         uint32_t a0, uint32_t a1, uint32_t a2, uint32_t a3,
                                         uint32_t b0, uint32_t b1) {
    asm volatile(
        "mma.sync.aligned.m16n8k16.row.col.f32.bf16.bf16.f32 "
        "{%0,%1,%2,%3}, {%4,%5,%6,%7}, {%8,%9}, {%0,%1,%2,%3};"
        : "+f"(c0), "+f"(c1), "+f"(c2), "+f"(c3)
        : "r"(a0), "r"(a1), "r"(a2), "r"(a3), "r"(b0), "r"(b1));
}

#define SW128(o) ((o) ^ (((o) >> 3) & 0x70))

// ---------------------------------------------------------------------------
// GEMM: C[m][n] = sum_k (Ahi+Alo)[m][k]*(Bhi+Blo)[n][k] + bias[n]
// 3 bf16 passes (hi*hi, lo*hi, hi*lo), fp32 accum.
// CTA tile 128x128, BK=64 (128B SW128 rows), 3-stage cp.async.
// 4 warps: 2(M) x 2(N), warp tile 64x64, mma.sync.m16n8k16.
// 2 CTAs/SM so stage barriers in one CTA overlap the other's MMAs.
// ---------------------------------------------------------------------------
#define GK      1024
#define BMT     128
#define BNT     128
#define NSTG    3
#define NK      48          // 3 passes * (1024/64)
#define STG_A   16384       // 128 rows * 128 B
#define STG_SZ  32768       // + 128 rows * 128 B
#define SMEM_DYN (1024 + NSTG * STG_SZ)

__device__ __forceinline__ void load_stage_g(
    uint32_t aBase, uint32_t bBase,
    const __nv_bfloat16* __restrict__ Ab, const __nv_bfloat16* __restrict__ Bb,
    int bm, int bn, int k0, int tid)
{
    #pragma unroll
    for (int q = 0; q < 8; q++) {           // A: 128 rows x 8 chunks = 1024
        int idx = tid + q * 128;
        int row = idx >> 3, c16 = idx & 7;
        const void* src = Ab + (size_t)(bm + row) * GK + k0 + c16 * 8;
        cp_async16(aBase + SW128(row * 128 + c16 * 16), src);
    }
    #pragma unroll
    for (int q = 0; q < 8; q++) {           // B: 128 rows x 8 chunks = 1024
        int idx = tid + q * 128;
        int row = idx >> 3, c16 = idx & 7;
        const void* src = Bb + (size_t)(bn + row) * GK + k0 + c16 * 8;
        cp_async16(bBase + SW128(row * 128 + c16 * 16), src);
    }
}

__global__ __launch_bounds__(128, 2)
void gemm3bf16(const __nv_bfloat16* __restrict__ Ahi, const __nv_bfloat16* __restrict__ Alo,
               const __nv_bfloat16* __restrict__ Bhi, const __nv_bfloat16* __restrict__ Blo,
               const float* __restrict__ bias, float* __restrict__ C, int Ntot)
{
    extern __shared__ char dsm[];
    const int tid  = threadIdx.x;
    const int wid  = tid >> 5;
    const int lane = tid & 31;
    const int wm   = wid & 1;       // 0..1  -> 64-row slab
    const int wn   = wid >> 1;      // 0..1  -> 64-col slab
    const int bn   = blockIdx.x * BNT;
    const int bm   = blockIdx.y * BMT;

    const uint32_t tiles = (smem_u32(dsm) + 1023u) & ~1023u;

    float acc[4][8][4];
    #pragma unroll
    for (int i = 0; i < 4; i++)
        #pragma unroll
        for (int j = 0; j < 8; j++)
            #pragma unroll
            for (int q = 0; q < 4; q++) acc[i][j][q] = 0.0f;

    // per-lane ldmatrix base byte-offsets (within tile, pre-swizzle)
    uint32_t baseA[4], baseB[4];
    #pragma unroll
    for (int mt = 0; mt < 4; mt++)
        baseA[mt] = (uint32_t)((wm * 64 + mt * 16 + (lane & 15)) * 128 + (lane >> 4) * 16);
    #pragma unroll
    for (int ntp = 0; ntp < 4; ntp++)
        baseB[ntp] = (uint32_t)((wn * 64 + ntp * 16 + ((lane >> 4) & 1) * 8 + (lane & 7)) * 128
                                + ((lane >> 3) & 1) * 16);

    // prologue: stages 0..NSTG-2
    #pragma unroll
    for (int j = 0; j < NSTG - 1; j++) {
        int p = j >> 4, k0 = (j & 15) << 6;
        const __nv_bfloat16* Aj = (p == 1) ? Alo : Ahi;
        const __nv_bfloat16* Bj = (p == 2) ? Blo : Bhi;
        uint32_t base = tiles + j * STG_SZ;
        load_stage_g(base, base + STG_A, Aj, Bj, bm, bn, k0, tid);
        CP_COMMIT();
    }

    int sl = 0;
    #pragma unroll 1
    for (int i = 0; i < NK; i++) {
        asm volatile("cp.async.wait_group %0;" :: "n"(NSTG - 2) : "memory");
        __syncthreads();

        // issue next stage load
        const int jn = i + NSTG - 1;
        if (jn < NK) {
            int p = jn >> 4, k0 = (jn & 15) << 6;
            const __nv_bfloat16* Aj = (p == 1) ? Alo : Ahi;
            const __nv_bfloat16* Bj = (p == 2) ? Blo : Bhi;
            int s2 = jn % NSTG;
            uint32_t base = tiles + s2 * STG_SZ;
            load_stage_g(base, base + STG_A, Aj, Bj, bm, bn, k0, tid);
        }
        CP_COMMIT();

        // compute slot sl
        const uint32_t aB = tiles + sl * STG_SZ;
        const uint32_t bB = aB + STG_A;
        #pragma unroll
        for (int ks = 0; ks < 4; ks++) {
            const uint32_t kb = ks * 32;
            uint32_t a[4][4];
            #pragma unroll
            for (int mt = 0; mt < 4; mt++) {
                uint32_t o = baseA[mt] + kb;
                ldm_x4(a[mt][0], a[mt][1], a[mt][2], a[mt][3], aB + SW128(o));
            }
            uint32_t b[16];
            #pragma unroll
            for (int ntp = 0; ntp < 4; ntp++) {
                uint32_t o = baseB[ntp] + kb;
                ldm_x4(b[ntp * 4 + 0], b[ntp * 4 + 1], b[ntp * 4 + 2], b[ntp * 4 + 3],
                       bB + SW128(o));
            }
            #pragma unroll
            for (int mt = 0; mt < 4; mt++)
                #pragma unroll
                for (int nt = 0; nt < 8; nt++)
                    mma16816(acc[mt][nt][0], acc[mt][nt][1], acc[mt][nt][2], acc[mt][nt][3],
                             a[mt][0], a[mt][1], a[mt][2], a[mt][3],
                             b[nt * 2], b[nt * 2 + 1]);
        }
        sl++; if (sl == NSTG) sl = 0;
    }

    // epilogue
    #pragma unroll
    for (int nt = 0; nt < 8; nt++) {
        const int col = bn + wn * 64 + nt * 8 + (lane & 3) * 2;
        const float b0 = bias[col], b1 = bias[col + 1];
        #pragma unroll
        for (int mt = 0; mt < 4; mt++) {
            const int row = bm + wm * 64 + mt * 16 + (lane >> 2);
            float2 v0, v1;
            v0.x = acc[mt][nt][0] + b0; v0.y = acc[mt][nt][1] + b1;
            v1.x = acc[mt][nt][2] + b0; v1.y = acc[mt][nt][3] + b1;
            *(float2*)(C + (size_t)row * Ntot + col)       = v0;
            *(float2*)(C + (size_t)(row + 8) * Ntot + col) = v1;
        }
    }
}

// ---------------------------------------------------------------------------
// Split fp32 -> (hi, lo) bf16
// ---------------------------------------------------------------------------
__global__ void split_bf16(const float4* __restrict__ in,
                           uint2* __restrict__ hi, uint2* __restrict__ lo, int n4)
{
    int i = blockIdx.x * blockDim.x + threadIdx.x;
    if (i >= n4) return;
    float4 v = in[i];
    __nv_bfloat16 h0 = __float2bfloat16(v.x);
    __nv_bfloat16 h1 = __float2bfloat16(v.y);
    __nv_bfloat16 h2 = __float2bfloat16(v.z);
    __nv_bfloat16 h3 = __float2bfloat16(v.w);
    __nv_bfloat16 l0 = __float2bfloat16(v.x - __bfloat162float(h0));
    __nv_bfloat16 l1 = __float2bfloat16(v.y - __bfloat162float(h1));
    __nv_bfloat16 l2 = __float2bfloat16(v.z - __bfloat162float(h2));
    __nv_bfloat16 l3 = __float2bfloat16(v.w - __bfloat162float(h3));
    uint2 ho, loo;
    ho.x  = (uint32_t)__bfloat16_as_ushort(h0) | ((uint32_t)__bfloat16_as_ushort(h1) << 16);
    ho.y  = (uint32_t)__bfloat16_as_ushort(h2) | ((uint32_t)__bfloat16_as_ushort(h3) << 16);
    loo.x = (uint32_t)__bfloat16_as_ushort(l0) | ((uint32_t)__bfloat16_as_ushort(l1) << 16);
    loo.y = (uint32_t)__bfloat16_as_ushort(l2) | ((uint32_t)__bfloat16_as_ushort(l3) << 16);
    hi[i] = ho;
    lo[i] = loo;
}

// ---------------------------------------------------------------------------
// Middle: per-head dynamic conv. Writes (hi, lo) bf16 split directly.
// ---------------------------------------------------------------------------
#define MTN    32
#define PADMAX 10

template <int KH>
__device__ __forceinline__ void mid_body(
    int h, int b, int n0, int d,
    float (*xs)[129], float* wcs, float (*as_)[KMAXK], float (*cs)[RR],
    const float* __restrict__ xproj, const float* __restrict__ Wc,
    const float* __restrict__ Aw, const float* __restrict__ Vw,
    const float* __restrict__ basew, const float* __restrict__ alphas,
    __nv_bfloat16* __restrict__ ohi, __nv_bfloat16* __restrict__ olo)
{
    const int pad = KH / 2;

    #pragma unroll
    for (int i = d; i < DH * RR; i += 128) wcs[i] = Wc[h * DH * RR + i];
    if (d < RR * KMAXK) ((float*)as_)[d] = Aw[h * RR * KMAXK + d];

    const float* xp = xproj + (size_t)b * SEQ * DMODEL + h * DH;
    const int nrows = MTN + 2 * pad;
    for (int r = 0; r < nrows; r++) {
        const int g = n0 - pad + r;
        xs[r][d] = (g >= 0 && g < SEQ) ? xp[(size_t)g * DMODEL + d] : 0.0f;
    }
    __syncthreads();

    {
        const int n = d >> 2, r = d & 3;
        float s = 0.0f;
        #pragma unroll 8
        for (int dd = 0; dd < DH; dd++)
            s += xs[pad + n][dd] * wcs[dd * RR + r];
        cs[n][r] = s;
    }
    __syncthreads();

    const float av    = alphas[h];
    const float alpha = 1.0f / (1.0f + __expf(-av));
    const float beta  = 1.0f - alpha;

    float vreg[RR];
    #pragma unroll
    for (int r = 0; r < RR; r++) vreg[r] = Vw[(h * RR + r) * DH + d];
    float breg[KH];
    #pragma unroll
    for (int j = 0; j < KH; j++) breg[j] = basew[(h * KMAXK + j) * DH + d];

    const size_t obase = ((size_t)b * SEQ + n0) * DMODEL + h * DH + d;
    #pragma unroll 4
    for (int ln = 0; ln < MTN; ln++) {
        float s0 = 0.f, s1 = 0.f, s2 = 0.f, s3 = 0.f, t = 0.f;
        #pragma unroll
        for (int j = 0; j < KH; j++) {
            const float w = xs[ln + j][d];
            s0 += as_[0][j] * w;
            s1 += as_[1][j] * w;
            s2 += as_[2][j] * w;
            s3 += as_[3][j] * w;
            t  += breg[j]   * w;
        }
        const float dyn = cs[ln][0] * vreg[0] * s0 + cs[ln][1] * vreg[1] * s1 +
                          cs[ln][2] * vreg[2] * s2 + cs[ln][3] * vreg[3] * s3;
        const float val = alpha * dyn + beta * t;
        const __nv_bfloat16 hi = __float2bfloat16(val);
        const __nv_bfloat16 lo = __float2bfloat16(val - __bfloat162float(hi));
        ohi[obase + (size_t)ln * DMODEL] = hi;
        olo[obase + (size_t)ln * DMODEL] = lo;
    }
}

__global__ __launch_bounds__(128)
void dka_mid_all(const float* __restrict__ xproj, const float* __restrict__ Wc,
                 const float* __restrict__ Aw, const float* __restrict__ Vw,
                 const float* __restrict__ basew, const float* __restrict__ alphas,
                 __nv_bfloat16* __restrict__ ohi, __nv_bfloat16* __restrict__ olo)
{
    __shared__ float xs[MTN + 2 * PADMAX][129];
    __shared__ float wcs[DH * RR];
    __shared__ float as_[RR][KMAXK];
    __shared__ float cs[MTN][RR];

    const int h  = blockIdx.z;
    const int b  = blockIdx.y;
    const int n0 = blockIdx.x * MTN;
    const int d  = threadIdx.x;

    switch (h >> 1) {
        case 0: mid_body< 3>(h, b, n0, d, xs, wcs, as_, cs, xproj, Wc, Aw, Vw, basew, alphas, ohi, olo); break;
        case 1: mid_body< 7>(h, b, n0, d, xs, wcs, as_, cs, xproj, Wc, Aw, Vw, basew, alphas, ohi, olo); break;
        case 2: mid_body<11>(h, b, n0, d, xs, wcs, as_, cs, xproj, Wc, Aw, Vw, basew, alphas, ohi, olo); break;
        default: mid_body<21>(h, b, n0, d, xs, wcs, as_, cs, xproj, Wc, Aw, Vw, basew, alphas, ohi, olo); break;
    }
}

// ---------------------------------------------------------------------------
// Launch
// ---------------------------------------------------------------------------
extern "C" void kernel_launch(void* const* d_in, const int* in_sizes, int n_in,
                              void* d_out, int out_size)
{
    const float* x      = (const float*)d_in[0];
    const float* W_in   = (const float*)d_in[1];
    const float* b_in   = (const float*)d_in[2];
    const float* W_out  = (const float*)d_in[3];
    const float* b_out  = (const float*)d_in[4];
    const float* Wc     = (const float*)d_in[5];
    const float* Aw     = (const float*)d_in[6];
    const float* Vw     = (const float*)d_in[7];
    const float* basew  = (const float*)d_in[8];
    const float* alphas = (const float*)d_in[9];
    float* out = (float*)d_out;

    float *xproj;
    __nv_bfloat16 *xhi, *xlo, *chi, *clo, *wihi, *wilo, *wohi, *wolo;
    cudaGetSymbolAddress((void**)&xproj, g_xproj);
    cudaGetSymbolAddress((void**)&xhi,  g_xhi);
    cudaGetSymbolAddress((void**)&xlo,  g_xlo);
    cudaGetSymbolAddress((void**)&chi,  g_chi);
    cudaGetSymbolAddress((void**)&clo,  g_clo);
    cudaGetSymbolAddress((void**)&wihi, g_wihi);
    cudaGetSymbolAddress((void**)&wilo, g_wilo);
    cudaGetSymbolAddress((void**)&wohi, g_wohi);
    cudaGetSymbolAddress((void**)&wolo, g_wolo);

    cudaFuncSetAttribute(gemm3bf16, cudaFuncAttributeMaxDynamicSharedMemorySize, SMEM_DYN);

    // splits
    {
        int n4x = MROWS * DMODEL / 4;
        int n4w = DMODEL * DMODEL / 4;
        split_bf16<<<(n4x + 255) / 256, 256>>>((const float4*)x, (uint2*)xhi, (uint2*)xlo, n4x);
        split_bf16<<<(n4w + 255) / 256, 256>>>((const float4*)W_in,  (uint2*)wihi, (uint2*)wilo, n4w);
        split_bf16<<<(n4w + 255) / 256, 256>>>((const float4*)W_out, (uint2*)wohi, (uint2*)wolo, n4w);
    }

    // GEMM 1: xproj = x @ W_in^T + b_in
    {
        dim3 grid(DMODEL / BNT, MROWS / BMT);
        gemm3bf16<<<grid, 128, SMEM_DYN>>>(xhi, xlo, wihi, wilo, b_in, xproj, DMODEL);
    }

    // Middle (single launch, all heads; writes chi/clo directly)
    {
        dim3 grid(SEQ / MTN, BATCH, NHEADS);
        dka_mid_all<<<grid, 128>>>(xproj, Wc, Aw, Vw, basew, alphas, chi, clo);
    }

    // GEMM 2: out = conc @ W_out^T + b_out
    {
        dim3 grid(DMODEL / BNT, MROWS / BMT);
        gemm3bf16<<<grid, 128, SMEM_DYN>>>(chi, clo, wohi, wolo, b_out, out, DMODEL);
    }
}

// round 12
// speedup vs baseline: 2.0863x; 2.0863x over previous
#include <cuda_runtime.h>
#include <cuda_fp16.h>
#include <cstdint>

// Problem constants
#define BATCH   2
#define SEQ     4096
#define DMODEL  1024
#define NHEADS  8
#define DH      128
#define RR      4
#define KMAXK   21
#define MROWS   (BATCH * SEQ)   // 8192

// ---------------------------------------------------------------------------
// Scratch (no cudaMalloc allowed)
// ---------------------------------------------------------------------------
__device__ float g_xproj[(size_t)MROWS * DMODEL];
__device__ __half g_xh [(size_t)MROWS * DMODEL];
__device__ __half g_ch [(size_t)MROWS * DMODEL];
__device__ __half g_wih[(size_t)DMODEL * DMODEL];
__device__ __half g_woh[(size_t)DMODEL * DMODEL];

// ---------------------------------------------------------------------------
// PTX helpers (sm_80-level only: cp.async, ldmatrix, mma.sync)
// ---------------------------------------------------------------------------
__device__ __forceinline__ uint32_t smem_u32(const void* p) {
    uint32_t a;
    asm("{ .reg .u64 t; cvta.to.shared.u64 t, %1; cvt.u32.u64 %0, t; }"
        : "=r"(a) : "l"(p));
    return a;
}

__device__ __forceinline__ void cp_async16(uint32_t dst, const void* src) {
    asm volatile("cp.async.cg.shared.global [%0], [%1], 16;"
                 :: "r"(dst), "l"(src));
}
#define CP_COMMIT() asm volatile("cp.async.commit_group;" ::: "memory")

__device__ __forceinline__ void ldm_x4(uint32_t& r0, uint32_t& r1,
                                       uint32_t& r2, uint32_t& r3, uint32_t addr) {
    asm volatile("ldmatrix.sync.aligned.m8n8.x4.shared.b16 {%0,%1,%2,%3}, [%4];"
                 : "=r"(r0), "=r"(r1), "=r"(r2), "=r"(r3) : "r"(addr));
}

__device__ __forceinline__ void mma16816(float& c0, float& c1, float& c2, float& c3,
                                         uint32_t a0, uint32_t a1, uint32_t a2, uint32_t a3,
                                         uint32_t b0, uint32_t b1) {
    asm volatile(
        "mma.sync.aligned.m16n8k16.row.col.f32.f16.f16.f32 "
        "{%0,%1,%2,%3}, {%4,%5,%6,%7}, {%8,%9}, {%0,%1,%2,%3};"
        : "+f"(c0), "+f"(c1), "+f"(c2), "+f"(c3)
        : "r"(a0), "r"(a1), "r"(a2), "r"(a3), "r"(b0), "r"(b1));
}

#define SW128(o) ((o) ^ (((o) >> 3) & 0x70))

// ---------------------------------------------------------------------------
// GEMM: C[m][n] = sum_k A[m][k]*Bt[n][k] + bias[n]   (fp16 inputs, fp32 accum)
// CTA tile 128x256, BK=64 (128B SW128 rows), 4-stage cp.async.
// 8 warps: 2(M) x 4(N), warp tile 64x64, mma.sync.m16n8k16.
// ---------------------------------------------------------------------------
#define GK      1024
#define BMT     128
#define BNT     256
#define NSTG    4
#define NK      16          // 1024/64
#define STG_A   16384       // 128 rows * 128 B
#define STG_SZ  49152       // + 256 rows * 128 B
#define SMEM_DYN (1024 + NSTG * STG_SZ)

__device__ __forceinline__ void load_stage_g(
    uint32_t aBase, uint32_t bBase,
    const __half* __restrict__ Ab, const __half* __restrict__ Bb,
    int bm, int bn, int k0, int tid)
{
    #pragma unroll
    for (int q = 0; q < 4; q++) {           // A: 128 rows x 8 chunks = 1024
        int idx = tid + q * 256;
        int row = idx >> 3, c16 = idx & 7;
        const void* src = Ab + (size_t)(bm + row) * GK + k0 + c16 * 8;
        cp_async16(aBase + SW128(row * 128 + c16 * 16), src);
    }
    #pragma unroll
    for (int q = 0; q < 8; q++) {           // B: 256 rows x 8 chunks = 2048
        int idx = tid + q * 256;
        int row = idx >> 3, c16 = idx & 7;
        const void* src = Bb + (size_t)(bn + row) * GK + k0 + c16 * 8;
        cp_async16(bBase + SW128(row * 128 + c16 * 16), src);
    }
}

__global__ __launch_bounds__(256, 1)
void gemm_fp16(const __half* __restrict__ A, const __half* __restrict__ Bt,
               const float* __restrict__ bias, float* __restrict__ C, int Ntot)
{
    extern __shared__ char dsm[];
    const int tid  = threadIdx.x;
    const int wid  = tid >> 5;
    const int lane = tid & 31;
    const int wm   = wid & 1;       // 0..1  -> 64-row slab
    const int wn   = wid >> 1;      // 0..3  -> 64-col slab
    const int bn   = blockIdx.x * BNT;
    const int bm   = blockIdx.y * BMT;

    const uint32_t tiles = (smem_u32(dsm) + 1023u) & ~1023u;

    float acc[4][8][4];
    #pragma unroll
    for (int i = 0; i < 4; i++)
        #pragma unroll
        for (int j = 0; j < 8; j++)
            #pragma unroll
            for (int q = 0; q < 4; q++) acc[i][j][q] = 0.0f;

    // per-lane ldmatrix base byte-offsets (within tile, pre-swizzle)
    uint32_t baseA[4], baseB[4];
    #pragma unroll
    for (int mt = 0; mt < 4; mt++)
        baseA[mt] = (uint32_t)((wm * 64 + mt * 16 + (lane & 15)) * 128 + (lane >> 4) * 16);
    #pragma unroll
    for (int ntp = 0; ntp < 4; ntp++)
        baseB[ntp] = (uint32_t)((wn * 64 + ntp * 16 + ((lane >> 4) & 1) * 8 + (lane & 7)) * 128
                                + ((lane >> 3) & 1) * 16);

    // prologue: stages 0..NSTG-2
    #pragma unroll
    for (int j = 0; j < NSTG - 1; j++) {
        int k0 = j << 6;
        uint32_t base = tiles + j * STG_SZ;
        load_stage_g(base, base + STG_A, A, Bt, bm, bn, k0, tid);
        CP_COMMIT();
    }

    int sl = 0;
    #pragma unroll 1
    for (int i = 0; i < NK; i++) {
        asm volatile("cp.async.wait_group %0;" :: "n"(NSTG - 2) : "memory");
        __syncthreads();

        // issue next stage load
        const int jn = i + NSTG - 1;
        if (jn < NK) {
            int k0 = jn << 6;
            int s2 = jn % NSTG;
            uint32_t base = tiles + s2 * STG_SZ;
            load_stage_g(base, base + STG_A, A, Bt, bm, bn, k0, tid);
        }
        CP_COMMIT();

        // compute slot sl
        const uint32_t aB = tiles + sl * STG_SZ;
        const uint32_t bB = aB + STG_A;
        #pragma unroll
        for (int ks = 0; ks < 4; ks++) {
            const uint32_t kb = ks * 32;
            uint32_t a[4][4];
            #pragma unroll
            for (int mt = 0; mt < 4; mt++) {
                uint32_t o = baseA[mt] + kb;
                ldm_x4(a[mt][0], a[mt][1], a[mt][2], a[mt][3], aB + SW128(o));
            }
            uint32_t b[16];
            #pragma unroll
            for (int ntp = 0; ntp < 4; ntp++) {
                uint32_t o = baseB[ntp] + kb;
                ldm_x4(b[ntp * 4 + 0], b[ntp * 4 + 1], b[ntp * 4 + 2], b[ntp * 4 + 3],
                       bB + SW128(o));
            }
            #pragma unroll
            for (int mt = 0; mt < 4; mt++)
                #pragma unroll
                for (int nt = 0; nt < 8; nt++)
                    mma16816(acc[mt][nt][0], acc[mt][nt][1], acc[mt][nt][2], acc[mt][nt][3],
                             a[mt][0], a[mt][1], a[mt][2], a[mt][3],
                             b[nt * 2], b[nt * 2 + 1]);
        }
        sl++; if (sl == NSTG) sl = 0;
    }

    // epilogue
    #pragma unroll
    for (int nt = 0; nt < 8; nt++) {
        const int col = bn + wn * 64 + nt * 8 + (lane & 3) * 2;
        const float b0 = bias[col], b1 = bias[col + 1];
        #pragma unroll
        for (int mt = 0; mt < 4; mt++) {
            const int row = bm + wm * 64 + mt * 16 + (lane >> 2);
            float2 v0, v1;
            v0.x = acc[mt][nt][0] + b0; v0.y = acc[mt][nt][1] + b1;
            v1.x = acc[mt][nt][2] + b0; v1.y = acc[mt][nt][3] + b1;
            *(float2*)(C + (size_t)row * Ntot + col)       = v0;
            *(float2*)(C + (size_t)(row + 8) * Ntot + col) = v1;
        }
    }
}

// ---------------------------------------------------------------------------
// Convert fp32 -> fp16
// ---------------------------------------------------------------------------
__global__ void conv_fp16(const float4* __restrict__ in, uint2* __restrict__ out, int n4)
{
    int i = blockIdx.x * blockDim.x + threadIdx.x;
    if (i >= n4) return;
    float4 v = in[i];
    __half2 p0 = __floats2half2_rn(v.x, v.y);
    __half2 p1 = __floats2half2_rn(v.z, v.w);
    uint2 o;
    o.x = *(uint32_t*)&p0;
    o.y = *(uint32_t*)&p1;
    out[i] = o;
}

// ---------------------------------------------------------------------------
// Middle: per-head dynamic conv. Writes fp16 directly.
// ---------------------------------------------------------------------------
#define MTN    32
#define PADMAX 10

template <int KH>
__device__ __forceinline__ void mid_body(
    int h, int b, int n0, int d,
    float (*xs)[129], float* wcs, float (*as_)[KMAXK], float (*cs)[RR],
    const float* __restrict__ xproj, const float* __restrict__ Wc,
    const float* __restrict__ Aw, const float* __restrict__ Vw,
    const float* __restrict__ basew, const float* __restrict__ alphas,
    __half* __restrict__ oh)
{
    const int pad = KH / 2;

    #pragma unroll
    for (int i = d; i < DH * RR; i += 128) wcs[i] = Wc[h * DH * RR + i];
    if (d < RR * KMAXK) ((float*)as_)[d] = Aw[h * RR * KMAXK + d];

    const float* xp = xproj + (size_t)b * SEQ * DMODEL + h * DH;
    const int nrows = MTN + 2 * pad;
    for (int r = 0; r < nrows; r++) {
        const int g = n0 - pad + r;
        xs[r][d] = (g >= 0 && g < SEQ) ? xp[(size_t)g * DMODEL + d] : 0.0f;
    }
    __syncthreads();

    {
        const int n = d >> 2, r = d & 3;
        float s = 0.0f;
        #pragma unroll 8
        for (int dd = 0; dd < DH; dd++)
            s += xs[pad + n][dd] * wcs[dd * RR + r];
        cs[n][r] = s;
    }
    __syncthreads();

    const float av    = alphas[h];
    const float alpha = 1.0f / (1.0f + __expf(-av));
    const float beta  = 1.0f - alpha;

    float vreg[RR];
    #pragma unroll
    for (int r = 0; r < RR; r++) vreg[r] = Vw[(h * RR + r) * DH + d];
    float breg[KH];
    #pragma unroll
    for (int j = 0; j < KH; j++) breg[j] = basew[(h * KMAXK + j) * DH + d];

    const size_t obase = ((size_t)b * SEQ + n0) * DMODEL + h * DH + d;
    #pragma unroll 4
    for (int ln = 0; ln < MTN; ln++) {
        float s0 = 0.f, s1 = 0.f, s2 = 0.f, s3 = 0.f, t = 0.f;
        #pragma unroll
        for (int j = 0; j < KH; j++) {
            const float w = xs[ln + j][d];
            s0 += as_[0][j] * w;
            s1 += as_[1][j] * w;
            s2 += as_[2][j] * w;
            s3 += as_[3][j] * w;
            t  += breg[j]   * w;
        }
        const float dyn = cs[ln][0] * vreg[0] * s0 + cs[ln][1] * vreg[1] * s1 +
                          cs[ln][2] * vreg[2] * s2 + cs[ln][3] * vreg[3] * s3;
        const float val = alpha * dyn + beta * t;
        oh[obase + (size_t)ln * DMODEL] = __float2half(val);
    }
}

__global__ __launch_bounds__(128)
void dka_mid_all(const float* __restrict__ xproj, const float* __restrict__ Wc,
                 const float* __restrict__ Aw, const float* __restrict__ Vw,
                 const float* __restrict__ basew, const float* __restrict__ alphas,
                 __half* __restrict__ oh)
{
    __shared__ float xs[MTN + 2 * PADMAX][129];
    __shared__ float wcs[DH * RR];
    __shared__ float as_[RR][KMAXK];
    __shared__ float cs[MTN][RR];

    const int h  = blockIdx.z;
    const int b  = blockIdx.y;
    const int n0 = blockIdx.x * MTN;
    const int d  = threadIdx.x;

    switch (h >> 1) {
        case 0: mid_body< 3>(h, b, n0, d, xs, wcs, as_, cs, xproj, Wc, Aw, Vw, basew, alphas, oh); break;
        case 1: mid_body< 7>(h, b, n0, d, xs, wcs, as_, cs, xproj, Wc, Aw, Vw, basew, alphas, oh); break;
        case 2: mid_body<11>(h, b, n0, d, xs, wcs, as_, cs, xproj, Wc, Aw, Vw, basew, alphas, oh); break;
        default: mid_body<21>(h, b, n0, d, xs, wcs, as_, cs, xproj, Wc, Aw, Vw, basew, alphas, oh); break;
    }
}

// ---------------------------------------------------------------------------
// Launch
// ---------------------------------------------------------------------------
extern "C" void kernel_launch(void* const* d_in, const int* in_sizes, int n_in,
                              void* d_out, int out_size)
{
    const float* x      = (const float*)d_in[0];
    const float* W_in   = (const float*)d_in[1];
    const float* b_in   = (const float*)d_in[2];
    const float* W_out  = (const float*)d_in[3];
    const float* b_out  = (const float*)d_in[4];
    const float* Wc     = (const float*)d_in[5];
    const float* Aw     = (const float*)d_in[6];
    const float* Vw     = (const float*)d_in[7];
    const float* basew  = (const float*)d_in[8];
    const float* alphas = (const float*)d_in[9];
    float* out = (float*)d_out;

    float *xproj;
    __half *xh, *ch, *wih, *woh;
    cudaGetSymbolAddress((void**)&xproj, g_xproj);
    cudaGetSymbolAddress((void**)&xh,  g_xh);
    cudaGetSymbolAddress((void**)&ch,  g_ch);
    cudaGetSymbolAddress((void**)&wih, g_wih);
    cudaGetSymbolAddress((void**)&woh, g_woh);

    cudaFuncSetAttribute(gemm_fp16, cudaFuncAttributeMaxDynamicSharedMemorySize, SMEM_DYN);

    // converts
    {
        int n4x = MROWS * DMODEL / 4;
        int n4w = DMODEL * DMODEL / 4;
        conv_fp16<<<(n4x + 255) / 256, 256>>>((const float4*)x, (uint2*)xh, n4x);
        conv_fp16<<<(n4w + 255) / 256, 256>>>((const float4*)W_in,  (uint2*)wih, n4w);
        conv_fp16<<<(n4w + 255) / 256, 256>>>((const float4*)W_out, (uint2*)woh, n4w);
    }

    // GEMM 1: xproj = x @ W_in^T + b_in
    {
        dim3 grid(DMODEL / BNT, MROWS / BMT);
        gemm_fp16<<<grid, 256, SMEM_DYN>>>(xh, wih, b_in, xproj, DMODEL);
    }

    // Middle (single launch, all heads; writes fp16 ch directly)
    {
        dim3 grid(SEQ / MTN, BATCH, NHEADS);
        dka_mid_all<<<grid, 128>>>(xproj, Wc, Aw, Vw, basew, alphas, ch);
    }

    // GEMM 2: out = conc @ W_out^T + b_out
    {
        dim3 grid(DMODEL / BNT, MROWS / BMT);
        gemm_fp16<<<grid, 256, SMEM_DYN>>>(ch, woh, b_out, out, DMODEL);
    }
}